// round 6
// baseline (speedup 1.0000x reference)
#include <cuda_runtime.h>
#include <math.h>

#define Bsz  4
#define Tlen 512
#define Edim 1024
#define Vdim 32000
#define GDIM (4*Edim)           // 4096 gate width
#define MROWS (Tlen*Bsz)        // 2048
#define NBLK 128                // persistent blocks for recurrence
#define LOGB (-1.0005003335835335e-3)    // log(1 - 0.001), double

// ---------------- scratch (static device globals; no allocation) ----------------
static __device__ __align__(16) float g_x    [MROWS * Edim];        // [T,B,E] embedded input
static __device__ __align__(16) float g_gates[MROWS * GDIM];        // [T,B,4E] ih-gates (+bias)
static __device__ __align__(16) float g_h0   [(Tlen+1) * Bsz*Edim]; // layer0 h sequence
static __device__ __align__(16) float g_h1   [(Tlen+1) * Bsz*Edim]; // layer1 h sequence

// grid-barrier state
static __device__ unsigned int g_arrive;
static __device__ unsigned int g_release;

__global__ void bar_reset() { g_arrive = 0; g_release = 0; }

// ---------------- helpers ----------------
__device__ __forceinline__ float tanh_acc(float x) {   // expf-based, ~1e-7 rel err
    float ax = fabsf(x);
    float t  = expf(-2.f * ax);
    float r  = (1.f - t) / (1.f + t);
    return copysignf(r, x);
}
__device__ __forceinline__ float sigm(float x) { return 1.f / (1.f + expf(-x)); }

// GPU-scope grid barrier (called by tid==0 of every block).
__device__ __forceinline__ void grid_barrier_t0(unsigned int gen) {
    __threadfence();
    unsigned int prev = atomicAdd(&g_arrive, 1u);
    if (prev + 1u == gen * NBLK) {
        __threadfence();
        asm volatile("st.release.gpu.u32 [%0], %1;"
                     :: "l"(&g_release), "r"(gen) : "memory");
    } else {
        unsigned int v;
        do {
            asm volatile("ld.acquire.gpu.u32 %0, [%1];"
                         : "=r"(v) : "l"(&g_release) : "memory");
        } while (v < gen);
    }
}

// ---------------- embedding: x[t,b,:] = emb[tokens[b,t]] ----------------
__global__ void embed_kernel(const int* __restrict__ tokens, const float* __restrict__ emb) {
    int id = blockIdx.x * blockDim.x + threadIdx.x;
    const int EV = Edim / 4;
    if (id >= MROWS * EV) return;
    int e4 = id % EV;
    int m  = id / EV;           // m = t*B + b
    int b  = m & 3, t = m >> 2;
    int tok = tokens[b * Tlen + t];
    ((float4*)g_x)[id] = ((const float4*)(emb + (size_t)tok * Edim))[e4];
}

// ---------------- SGEMM (NT): C[m,n] = sum_k A[m,k]*B[n,k] + bias1[n] + bias2[n] ----------------
__global__ __launch_bounds__(256, 2)
void gemm_nt(const float* __restrict__ A, const float* __restrict__ B,
             float* __restrict__ C, int M, int N, int K,
             const float* __restrict__ bias1, const float* __restrict__ bias2,
             int remap)
{
    __shared__ __align__(16) float As[8][132];
    __shared__ __align__(16) float Bs[8][132];
    const int tid  = threadIdx.x;
    const int row0 = blockIdx.y * 128;
    const int col0 = blockIdx.x * 128;
    const int lr = tid >> 1;
    const int lc = (tid & 1) * 4;
    const int ty = tid >> 4;
    const int tx = tid & 15;

    const float* Aptr = A + (size_t)(row0 + lr) * K + lc;
    const float* Bptr = B + (size_t)(col0 + lr) * K + lc;

    float acc[8][8];
#pragma unroll
    for (int i = 0; i < 8; i++)
#pragma unroll
        for (int j = 0; j < 8; j++) acc[i][j] = 0.f;

    for (int kb = 0; kb < K; kb += 8) {
        float4 av = *(const float4*)(Aptr + kb);
        float4 bv = *(const float4*)(Bptr + kb);
        As[lc + 0][lr] = av.x; As[lc + 1][lr] = av.y; As[lc + 2][lr] = av.z; As[lc + 3][lr] = av.w;
        Bs[lc + 0][lr] = bv.x; Bs[lc + 1][lr] = bv.y; Bs[lc + 2][lr] = bv.z; Bs[lc + 3][lr] = bv.w;
        __syncthreads();
#pragma unroll
        for (int kk = 0; kk < 8; kk++) {
            float4 a0 = *(const float4*)&As[kk][ty * 8];
            float4 a1 = *(const float4*)&As[kk][ty * 8 + 4];
            float4 b0 = *(const float4*)&Bs[kk][tx * 8];
            float4 b1 = *(const float4*)&Bs[kk][tx * 8 + 4];
            float a[8] = {a0.x, a0.y, a0.z, a0.w, a1.x, a1.y, a1.z, a1.w};
            float b[8] = {b0.x, b0.y, b0.z, b0.w, b1.x, b1.y, b1.z, b1.w};
#pragma unroll
            for (int i = 0; i < 8; i++)
#pragma unroll
                for (int j = 0; j < 8; j++) acc[i][j] = fmaf(a[i], b[j], acc[i][j]);
        }
        __syncthreads();
    }

    float bsave[8];
#pragma unroll
    for (int j = 0; j < 8; j++) {
        int n = col0 + tx * 8 + j;
        float bvv = 0.f;
        if (bias1) bvv += bias1[n];
        if (bias2) bvv += bias2[n];
        bsave[j] = bvv;
    }
#pragma unroll
    for (int i = 0; i < 8; i++) {
        int m = row0 + ty * 8 + i;
        int orow = remap ? ((m & 3) * Tlen + (m >> 2)) : m;
        float* crow = C + (size_t)orow * N + col0 + tx * 8;
        float4 v0, v1;
        v0.x = acc[i][0] + bsave[0]; v0.y = acc[i][1] + bsave[1];
        v0.z = acc[i][2] + bsave[2]; v0.w = acc[i][3] + bsave[3];
        v1.x = acc[i][4] + bsave[4]; v1.y = acc[i][5] + bsave[5];
        v1.z = acc[i][6] + bsave[6]; v1.w = acc[i][7] + bsave[7];
        *(float4*)(crow)     = v0;
        *(float4*)(crow + 4) = v1;
    }
}

// ---------------- persistent LSTM layer ----------------
__global__ void __launch_bounds__(256, 1)
lstm_layer(const float* __restrict__ gih,   // [T,B,4E] input gates (bias included)
           const float* __restrict__ Whh,   // [4E,E]
           float* __restrict__ hseq)        // [T+1,B,E]; slots 1..T written
{
    extern __shared__ float sm[];
    float* ws   = sm;                  // [32][1024] weight rows (gate*8 + j)
    float* hs   = ws + 32 * 1024;      // [4][1024] h_prev
    float* garr = hs + 4 * 1024;       // [4 gates][4 b][8 j]
    float* cs   = garr + 128;          // [4 b][8 j] cell state

    const int blk  = blockIdx.x;       // 0..127
    const int e0   = blk * 8;
    const int tid  = threadIdx.x;
    const int warp = tid >> 5;
    const int lane = tid & 31;

    // load Whh slice: smem row r = g*8+j <- global row g*Edim + e0 + j
    for (int r = warp; r < 32; r += 8) {
        int g = r >> 3, j = r & 7;
        const float* src = Whh + (size_t)(g * Edim + e0 + j) * Edim;
        for (int c = lane * 4; c < Edim; c += 128)
            *(float4*)&ws[r * 1024 + c] = *(const float4*)&src[c];
    }
    if (tid < 32) cs[tid] = 0.f;
    __syncthreads();

    const int r0 = warp * 4;
    const float* wr0 = ws + (r0 + 0) * 1024;
    const float* wr1 = ws + (r0 + 1) * 1024;
    const float* wr2 = ws + (r0 + 2) * 1024;
    const float* wr3 = ws + (r0 + 3) * 1024;

    for (int t = 0; t < Tlen; t++) {
        // load h_prev
        if (t == 0) {
            for (int i = tid; i < 4096; i += 256) hs[i] = 0.f;
        } else {
            const float4* hp = (const float4*)(hseq + (size_t)t * (Bsz * Edim));
            float4* hd = (float4*)hs;
            for (int i = tid; i < 1024; i += 256) hd[i] = hp[i];
        }
        __syncthreads();

        float a00=0,a01=0,a02=0,a03=0, a10=0,a11=0,a12=0,a13=0;
        float a20=0,a21=0,a22=0,a23=0, a30=0,a31=0,a32=0,a33=0;
#pragma unroll 4
        for (int kc = lane; kc < Edim; kc += 32) {
            float h0 = hs[kc], h1 = hs[kc + 1024], h2 = hs[kc + 2048], h3 = hs[kc + 3072];
            float w0 = wr0[kc], w1 = wr1[kc], w2 = wr2[kc], w3 = wr3[kc];
            a00 = fmaf(w0, h0, a00); a01 = fmaf(w0, h1, a01); a02 = fmaf(w0, h2, a02); a03 = fmaf(w0, h3, a03);
            a10 = fmaf(w1, h0, a10); a11 = fmaf(w1, h1, a11); a12 = fmaf(w1, h2, a12); a13 = fmaf(w1, h3, a13);
            a20 = fmaf(w2, h0, a20); a21 = fmaf(w2, h1, a21); a22 = fmaf(w2, h2, a22); a23 = fmaf(w2, h3, a23);
            a30 = fmaf(w3, h0, a30); a31 = fmaf(w3, h1, a31); a32 = fmaf(w3, h2, a32); a33 = fmaf(w3, h3, a33);
        }
#pragma unroll
        for (int off = 16; off; off >>= 1) {
            a00 += __shfl_down_sync(~0u, a00, off); a01 += __shfl_down_sync(~0u, a01, off);
            a02 += __shfl_down_sync(~0u, a02, off); a03 += __shfl_down_sync(~0u, a03, off);
            a10 += __shfl_down_sync(~0u, a10, off); a11 += __shfl_down_sync(~0u, a11, off);
            a12 += __shfl_down_sync(~0u, a12, off); a13 += __shfl_down_sync(~0u, a13, off);
            a20 += __shfl_down_sync(~0u, a20, off); a21 += __shfl_down_sync(~0u, a21, off);
            a22 += __shfl_down_sync(~0u, a22, off); a23 += __shfl_down_sync(~0u, a23, off);
            a30 += __shfl_down_sync(~0u, a30, off); a31 += __shfl_down_sync(~0u, a31, off);
            a32 += __shfl_down_sync(~0u, a32, off); a33 += __shfl_down_sync(~0u, a33, off);
        }
        if (lane == 0) {
            float vals[4][4] = {{a00,a01,a02,a03},{a10,a11,a12,a13},
                                {a20,a21,a22,a23},{a30,a31,a32,a33}};
#pragma unroll
            for (int rr = 0; rr < 4; rr++) {
                int r = r0 + rr, g = r >> 3, j = r & 7;
#pragma unroll
                for (int b = 0; b < 4; b++)
                    garr[(g * 4 + b) * 8 + j] = vals[rr][b];
            }
        }
        __syncthreads();

        if (tid < 32) {
            int b = tid >> 3, j = tid & 7, e = e0 + j;
            const float* gb = gih + ((size_t)t * Bsz + b) * GDIM;
            float gi = garr[(0 * 4 + b) * 8 + j] + gb[e];
            float gf = garr[(1 * 4 + b) * 8 + j] + gb[Edim + e];
            float gG = garr[(2 * 4 + b) * 8 + j] + gb[2 * Edim + e];
            float go = garr[(3 * 4 + b) * 8 + j] + gb[3 * Edim + e];
            float c = sigm(gf) * cs[tid] + sigm(gi) * tanh_acc(gG);
            cs[tid] = c;
            hseq[(size_t)(t + 1) * (Bsz * Edim) + b * Edim + e] = sigm(go) * tanh_acc(c);
        }
        __syncthreads();

        if (tid == 0) grid_barrier_t0((unsigned int)(t + 1));
        __syncthreads();
    }
}

// ---------------- post-processing (in place on d_out) ----------------
__global__ void postprocess(float* __restrict__ out) {
    const int r = blockIdx.x;                   // 0..2047 (row = b*T + t)
    const int t_idx = r & (Tlen - 1);
    float* z = out + (size_t)r * Vdim;
    const int VV = Vdim - 1;
    const int tid = threadIdx.x;

    __shared__ float red[256];
    __shared__ float sh_shift, sh_eos;

    float mx = -3.402823466e38f;
    for (int v = tid; v < VV; v += 256) mx = fmaxf(mx, z[v]);
    red[tid] = mx; __syncthreads();
#pragma unroll
    for (int s = 128; s; s >>= 1) { if (tid < s) red[tid] = fmaxf(red[tid], red[tid + s]); __syncthreads(); }
    mx = red[0];
    __syncthreads();

    float sum = 0.f;
    for (int v = tid; v < VV; v += 256) sum += expf(z[v] - mx);
    red[tid] = sum; __syncthreads();
#pragma unroll
    for (int s = 128; s; s >>= 1) { if (tid < s) red[tid] += red[tid + s]; __syncthreads(); }

    if (tid == 0) {
        double lse = (double)mx + log((double)red[0]);
        double e   = (double)z[VV];
        double lsn = (-e < 0 ? -e : 0.0) - log1p(exp(-fabs(e)));  // log_sigmoid(-e)
        double lsp = ( e < 0 ?  e : 0.0) - log1p(exp(-fabs(e)));  // log_sigmoid(e)
        double log_lb = (double)(t_idx + 1) * LOGB;
        double C1 = log_lb + lsn;
        double log_lb_eos = log(-expm1(log_lb)) + lsn;
        double d = log_lb_eos - lsp;
        double logsig_d = (d < 0 ? d : 0.0) - log1p(exp(-fabs(d)));
        double lpe = log_lb_eos - logsig_d;
        double m2 = fmax(C1, lpe);
        double Z  = m2 + log1p(exp(fmin(C1, lpe) - m2));
        sh_shift = (float)(C1 - lse - Z);
        sh_eos   = (float)(lpe - Z);
    }
    __syncthreads();

    float shift = sh_shift;
    for (int v = tid; v < VV; v += 256) z[v] += shift;
    if (tid == 0) z[VV] = sh_eos;
}

// ---------------- launcher ----------------
extern "C" void kernel_launch(void* const* d_in, const int* in_sizes, int n_in,
                              void* d_out, int out_size)
{
    (void)in_sizes; (void)n_in; (void)out_size;
    // metadata order = setup_inputs() dict insertion order:
    // 0:tokens 1:emb 2:Wproj 3:Wih0 4:Whh0 5:bih0 6:bhh0 7:Wih1 8:Whh1 9:bih1 10:bhh1
    const int*   tokens = (const int*)  d_in[0];
    const float* emb    = (const float*)d_in[1];
    const float* Wproj  = (const float*)d_in[2];
    const float* Wih0   = (const float*)d_in[3];
    const float* Whh0   = (const float*)d_in[4];
    const float* bih0   = (const float*)d_in[5];
    const float* bhh0   = (const float*)d_in[6];
    const float* Wih1   = (const float*)d_in[7];
    const float* Whh1   = (const float*)d_in[8];
    const float* bih1   = (const float*)d_in[9];
    const float* bhh1   = (const float*)d_in[10];
    float* out = (float*)d_out;

    float *px, *pg, *ph0, *ph1;
    cudaGetSymbolAddress((void**)&px,  g_x);
    cudaGetSymbolAddress((void**)&pg,  g_gates);
    cudaGetSymbolAddress((void**)&ph0, g_h0);
    cudaGetSymbolAddress((void**)&ph1, g_h1);

    const int lstm_smem = (32 * 1024 + 4 * 1024 + 128 + 32) * (int)sizeof(float);
    cudaFuncSetAttribute(lstm_layer, cudaFuncAttributeMaxDynamicSharedMemorySize, lstm_smem);

    // 1. embedding
    embed_kernel<<<(MROWS * Edim / 4 + 255) / 256, 256>>>(tokens, emb);

    // 2. layer-0 input gates
    dim3 gg(GDIM / 128, MROWS / 128);       // (32, 16)
    gemm_nt<<<gg, 256>>>(px, Wih0, pg, MROWS, GDIM, Edim, bih0, bhh0, 0);

    // 3. layer-0 recurrence (persistent)
    bar_reset<<<1, 1>>>();
    lstm_layer<<<NBLK, 256, lstm_smem>>>(pg, Whh0, ph0);

    // 4. layer-1 input gates
    gemm_nt<<<gg, 256>>>(ph0 + Bsz * Edim, Wih1, pg, MROWS, GDIM, Edim, bih1, bhh1, 0);

    // 5. layer-1 recurrence (persistent)
    bar_reset<<<1, 1>>>();
    lstm_layer<<<NBLK, 256, lstm_smem>>>(pg, Whh1, ph1);

    // 6. projection -> logits directly into d_out (rows remapped to [B,T] order)
    dim3 gp(Vdim / 128, MROWS / 128);       // (250, 16)
    gemm_nt<<<gp, 256>>>(ph1 + Bsz * Edim, Wproj, out, MROWS, Vdim, Edim,
                         nullptr, nullptr, 1);

    // 7. log-prob post-processing in place
    postprocess<<<MROWS, 256>>>(out);
}